// round 9
// baseline (speedup 1.0000x reference)
#include <cuda_runtime.h>
#include <math.h>

#define TT   500
#define BB   256
#define ENCN 700
#define HIDN 128
#define LCAP 128          // max firing enc per (b,t); mean 35 -> huge margin
#define NTHD 32768        // BB*HIDN
#define CHB  64           // batch-chunk size (4 chunks pipelined)
#define NBATCH 50         // TT/10 scan batches

// ---------------- static device scratch (allocation-free rule) ----------------
__device__ float          g_w1t[ENCN * HIDN];                 // w1 transposed [enc][hid]
__device__ int            g_cnt [BB * TT];                    // firing count per (b,t)
__device__ unsigned short g_list[(size_t)BB * TT * LCAP];     // firing enc indices (ascending)
__device__ float          g_h   [(size_t)TT * BB * HIDN];     // layer-1 pre-filter activations
__device__ unsigned char  g_s1b [(size_t)TT * BB * HIDN];     // layer-1 spikes as bytes
__device__ float          g_o   [TT * BB];                    // layer-2 pre-filter input

// Constants exactly as XLA-on-GPU computes them (bit-exact — DO NOT TOUCH):
__device__ __forceinline__ void snn_consts(float& d, float& cd1, float& cdr) {
    d        = expf(-0.05f);          // libdevice __nv_expf
    float e1 = expf(1.0f);
    float c1 = __fdiv_rn(e1, 20.0f);
    cd1      = __fmul_rn(c1, d);
    float cr = __fdiv_rn(__fmul_rn(-2.0f, e1), 20.0f);
    cdr      = __fmul_rn(cr, d);
}

// ptxas-contracted scan step (bit-exact — DO NOT TOUCH):
__device__ __forceinline__ void alpha_step(float d, float cd, float& p, float& q, float in) {
    q = fmaf(d, q, __fmul_rn(cd, p));
    p = fmaf(d, p, in);
}

// ---------------- K_t: transpose w1 [hid][enc] -> [enc][hid] ----------------
__global__ void k_transpose(const float* __restrict__ w1) {
    int i = blockIdx.x * blockDim.x + threadIdx.x;
    if (i < ENCN * HIDN) {
        int e = i >> 7;
        int h = i & (HIDN - 1);
        g_w1t[i] = w1[h * ENCN + e];
    }
}

// ---------------- K0: ballot-compact firing enc indices per (b,t) ----------------
__global__ __launch_bounds__(256) void k_compact(const float* __restrict__ x, int b0) {
    int b    = b0 + blockIdx.y;
    int t    = blockIdx.x * 8 + (threadIdx.x >> 5);
    int lane = threadIdx.x & 31;
    if (t >= TT) return;

    const float4* xr4 = (const float4*)(x + (size_t)b * (TT * ENCN) + (size_t)t * ENCN);

    float4 v[6];
#pragma unroll
    for (int g = 0; g < 6; ++g) {
        int idx = g * 32 + lane;                 // float4 index, 175 per row
        v[g] = (idx < 175) ? __ldg(xr4 + idx)
                           : make_float4(0.f, 0.f, 0.f, 0.f);
    }

    unsigned short* lst = g_list + ((size_t)b * TT + t) * LCAP;
    const unsigned lt = (1u << lane) - 1u;
    int cnt = 0;
#pragma unroll
    for (int g = 0; g < 6; ++g) {
        bool f0 = v[g].x > 0.5f, f1 = v[g].y > 0.5f, f2 = v[g].z > 0.5f, f3 = v[g].w > 0.5f;
        unsigned m0 = __ballot_sync(0xffffffffu, f0);
        unsigned m1 = __ballot_sync(0xffffffffu, f1);
        unsigned m2 = __ballot_sync(0xffffffffu, f2);
        unsigned m3 = __ballot_sync(0xffffffffu, f3);
        int p = cnt + __popc(m0 & lt) + __popc(m1 & lt) + __popc(m2 & lt) + __popc(m3 & lt);
        int e0 = g * 128 + lane * 4;
        if (f0) { if (p < LCAP) lst[p] = (unsigned short)(e0 + 0); ++p; }
        if (f1) { if (p < LCAP) lst[p] = (unsigned short)(e0 + 1); ++p; }
        if (f2) { if (p < LCAP) lst[p] = (unsigned short)(e0 + 2); ++p; }
        if (f3) { if (p < LCAP) lst[p] = (unsigned short)(e0 + 3); ++p; }
        cnt += __popc(m0) + __popc(m1) + __popc(m2) + __popc(m3);
    }
    if (lane == 0) g_cnt[b * TT + t] = cnt < LCAP ? cnt : LCAP;
}

// ---------------- K_A: sparse gather GEMM (proven) ----------------
__global__ __launch_bounds__(512, 2) void k_gather(int b0) {
    extern __shared__ float w1s[];   // [700][32] = 89600 B
    const int b = b0 + blockIdx.x, hq = blockIdx.y;
    const int tid  = threadIdx.x;
    const int wid  = tid >> 5;
    const int lane = tid & 31;

    for (int i = tid; i < ENCN * 32; i += 512) {
        int e = i >> 5, h = i & 31;
        w1s[i] = g_w1t[e * HIDN + hq * 32 + h];
    }
    __syncthreads();

    for (int t = wid; t < TT; t += 16) {
        int base = b * TT + t;
        int n = __ldg(g_cnt + base);
        const uint4* l4 = (const uint4*)(g_list + (size_t)base * LCAP);

        uint4 v[6];
#pragma unroll
        for (int r = 0; r < 6; ++r)
            v[r] = (8 * r < n) ? __ldg(l4 + r) : make_uint4(0u, 0u, 0u, 0u);

        const int nfull = (n < 48 ? n : 48) >> 3;
        const int nrem  = (n < 48 ? n : 48) & 7;
        float acc = 0.0f;
#pragma unroll
        for (int r = 0; r < 6; ++r) {
            unsigned wrd[4] = { v[r].x, v[r].y, v[r].z, v[r].w };
            if (r < nfull) {
#pragma unroll
                for (int k = 0; k < 4; ++k) {
                    acc = __fadd_rn(acc, w1s[(int)(wrd[k] & 0xffffu) * 32 + lane]);
                    acc = __fadd_rn(acc, w1s[(int)(wrd[k] >> 16)     * 32 + lane]);
                }
            } else if (r == nfull && nrem) {
#pragma unroll
                for (int k = 0; k < 4; ++k) {
                    if (2 * k     < nrem) acc = __fadd_rn(acc, w1s[(int)(wrd[k] & 0xffffu) * 32 + lane]);
                    if (2 * k + 1 < nrem) acc = __fadd_rn(acc, w1s[(int)(wrd[k] >> 16)     * 32 + lane]);
                }
            }
        }
        const unsigned short* lst = g_list + (size_t)base * LCAP;
        for (int k = 48; k < n; ++k)
            acc = __fadd_rn(acc, w1s[lst[k] * 32 + lane]);

        g_h[(size_t)t * NTHD + b * HIDN + hq * 32 + lane] = acc;
    }
}

// ---------------- K_B: layer-1 scan, FULL batch, 4-deep rotating prefetch ----------------
__global__ __launch_bounds__(256, 1) void k_scan1() {
    int gid = blockIdx.x * 256 + threadIdx.x;   // b*128 + h

    float d, cd1, cdr;
    snn_consts(d, cd1, cdr);

    float p1 = 0.f, q1 = 0.f, pr = 0.f, qr = 0.f;
    float buf[4][10];

#pragma unroll
    for (int k = 0; k < 4; ++k)
#pragma unroll
        for (int j = 0; j < 10; ++j)
            buf[k][j] = __ldg(&g_h[(size_t)(k * 10 + j) * NTHD + gid]);

    for (int bi4 = 0; bi4 < NBATCH; bi4 += 4) {
#pragma unroll
        for (int s = 0; s < 4; ++s) {
            int bi = bi4 + s;
            if (bi < NBATCH) {
                int t0 = bi * 10;
#pragma unroll
                for (int j = 0; j < 10; ++j) {
                    alpha_step(d, cd1, p1, q1, buf[s][j]);
                    qr = fmaf(d, qr, __fmul_rn(cdr, pr));
                    float u = __fadd_rn(q1, qr);
                    float sv = (u >= 1.0f) ? 1.0f : 0.0f;
                    pr = fmaf(d, pr, sv);
                    g_s1b[(size_t)(t0 + j) * NTHD + gid] = (unsigned char)(u >= 1.0f);
                }
                int nb = bi + 4;
                if (nb < NBATCH) {
#pragma unroll
                    for (int j = 0; j < 10; ++j)
                        buf[s][j] = __ldg(&g_h[(size_t)(nb * 10 + j) * NTHD + gid]);
                }
            }
        }
    }
}

// ---------------- K_C: o[t,b] = serial ascending-h FFMA over byte spikes ----------------
__global__ __launch_bounds__(256) void k_dot2(const float* __restrict__ w2) {
    __shared__ float w2s[HIDN];
    if (threadIdx.x < HIDN) w2s[threadIdx.x] = w2[threadIdx.x];
    __syncthreads();

    int t = blockIdx.x;
    int b = threadIdx.x;
    const uint4* sp = (const uint4*)(g_s1b + (size_t)t * NTHD + b * HIDN);

    float acc = 0.0f;
#pragma unroll
    for (int j = 0; j < 8; ++j) {
        uint4 v = __ldg(sp + j);
        unsigned wrd[4] = { v.x, v.y, v.z, v.w };
#pragma unroll
        for (int k = 0; k < 4; ++k) {
            unsigned w = wrd[k];
            int base = j * 16 + k * 4;
            acc = fmaf((float)(w & 0xffu),         w2s[base + 0], acc);
            acc = fmaf((float)((w >> 8) & 0xffu),  w2s[base + 1], acc);
            acc = fmaf((float)((w >> 16) & 0xffu), w2s[base + 2], acc);
            acc = fmaf((float)(w >> 24),           w2s[base + 3], acc);
        }
    }
    g_o[t * BB + b] = acc;
}

// ---------------- K_D: layer-2 scan, FULL batch, 4-deep rotating prefetch ----------------
__global__ __launch_bounds__(BB, 1) void k_scan2(float* __restrict__ out) {
    int b = threadIdx.x;

    float d, cd1, cdr;
    snn_consts(d, cd1, cdr);

    float p2 = 0.f, q2 = 0.f, pr2 = 0.f, qr2 = 0.f;
    float buf[4][10];

#pragma unroll
    for (int k = 0; k < 4; ++k)
#pragma unroll
        for (int j = 0; j < 10; ++j)
            buf[k][j] = __ldg(&g_o[(k * 10 + j) * BB + b]);

    for (int bi4 = 0; bi4 < NBATCH; bi4 += 4) {
#pragma unroll
        for (int s = 0; s < 4; ++s) {
            int bi = bi4 + s;
            if (bi < NBATCH) {
                int t0 = bi * 10;
#pragma unroll
                for (int j = 0; j < 10; ++j) {
                    alpha_step(d, cd1, p2, q2, buf[s][j]);
                    qr2 = fmaf(d, qr2, __fmul_rn(cdr, pr2));
                    float u = __fadd_rn(q2, qr2);
                    float sv = (u >= 1.0f) ? 1.0f : 0.0f;
                    pr2 = fmaf(d, pr2, sv);
                    out[b * TT + (t0 + j)] = sv;
                }
                int nb = bi + 4;
                if (nb < NBATCH) {
#pragma unroll
                    for (int j = 0; j < 10; ++j)
                        buf[s][j] = __ldg(&g_o[(nb * 10 + j) * BB + b]);
                }
            }
        }
    }
}

// ---------------- launch: chunked compact/gather pipeline + full-batch scans ----------------
// EXACTLY 3 streams (4+ streams trips the device-memory guard — learned R8).
extern "C" void kernel_launch(void* const* d_in, const int* in_sizes, int n_in,
                              void* d_out, int out_size) {
    const float* x = nullptr, *w1 = nullptr, *w2 = nullptr;
    for (int i = 0; i < n_in; ++i) {
        if      (in_sizes[i] == BB * TT * ENCN) x  = (const float*)d_in[i];
        else if (in_sizes[i] == HIDN * ENCN)    w1 = (const float*)d_in[i];
        else if (in_sizes[i] == HIDN)           w2 = (const float*)d_in[i];
    }

    static cudaStream_t sC = 0, sG = 0, sS = 0;
    static cudaEvent_t  evFork, evC[4], evG[4], evS;
    static int inited = 0;
    if (!inited) {
        cudaFuncSetAttribute(k_gather, cudaFuncAttributeMaxDynamicSharedMemorySize,
                             ENCN * 32 * (int)sizeof(float));
        cudaStreamCreateWithFlags(&sC, cudaStreamNonBlocking);
        cudaStreamCreateWithFlags(&sG, cudaStreamNonBlocking);
        cudaStreamCreateWithFlags(&sS, cudaStreamNonBlocking);
        cudaEventCreateWithFlags(&evFork, cudaEventDisableTiming);
        cudaEventCreateWithFlags(&evS, cudaEventDisableTiming);
        for (int i = 0; i < 4; ++i) {
            cudaEventCreateWithFlags(&evC[i], cudaEventDisableTiming);
            cudaEventCreateWithFlags(&evG[i], cudaEventDisableTiming);
        }
        inited = 1;
    }

    cudaEventRecord(evFork, 0);
    cudaStreamWaitEvent(sC, evFork, 0);
    cudaStreamWaitEvent(sG, evFork, 0);

    k_transpose<<<(ENCN * HIDN + 255) / 256, 256, 0, sG>>>(w1);

    for (int i = 0; i < 4; ++i) {
        int b0 = i * CHB;
        // stage 1: compact (DRAM-bound), chunks serial on sC
        k_compact<<<dim3((TT + 7) / 8, CHB), 256, 0, sC>>>(x, b0);
        cudaEventRecord(evC[i], sC);
        // stage 2: gather (smem-bound) overlaps later compacts
        cudaStreamWaitEvent(sG, evC[i], 0);
        k_gather<<<dim3(CHB, 4), 512, ENCN * 32 * sizeof(float), sG>>>(b0);
        cudaEventRecord(evG[i], sG);
    }

    // stage 3: latency-bound scans ONCE, full batch, after last gather
    cudaStreamWaitEvent(sS, evG[3], 0);
    k_scan1<<<NTHD / 256, 256, 0, sS>>>();
    k_dot2<<<TT, BB, 0, sS>>>(w2);
    k_scan2<<<1, BB, 0, sS>>>((float*)d_out);
    cudaEventRecord(evS, sS);
    cudaStreamWaitEvent(0, evS, 0);
}